// round 1
// baseline (speedup 1.0000x reference)
#include <cuda_runtime.h>
#include <cstdint>

typedef unsigned long long ull;
#define DI __device__ __forceinline__

constexpr int NB   = 4;     // batch
constexpr int CT   = 256;   // channels
constexpr int LSEQ = 1024;  // sequence length
constexpr int NH   = 16;    // heads
constexpr int CK   = 128;   // CT/2 (k,q channels)

// ---------------- scratch (no cudaMalloc allowed) ----------------
__device__ float g_k  [NB*CK*LSEQ];
__device__ float g_q  [NB*CK*LSEQ];
__device__ float g_v  [NB*CT*LSEQ];
__device__ float g_t1 [NB*CT*LSEQ];   // tokens + kqv, [N][C][L]
__device__ float g_t1t[NB*LSEQ*CT];   // transposed copy, [N*L][C]
__device__ float g_xn [NB*LSEQ*CT];   // LN1 output, [N*L][C]
__device__ float g_h1 [NB*LSEQ*CT];   // FFN hidden
__device__ float g_ffn[NB*LSEQ*CT];   // FFN output

// ---------------- f32x2 helpers (Blackwell packed fp32) ----------------
DI ull fma2(ull a, ull b, ull c) {
    ull d; asm("fma.rn.f32x2 %0, %1, %2, %3;" : "=l"(d) : "l"(a), "l"(b), "l"(c)); return d;
}
DI ull mul2(ull a, ull b) {
    ull d; asm("mul.rn.f32x2 %0, %1, %2;" : "=l"(d) : "l"(a), "l"(b)); return d;
}
DI ull pk2(float lo, float hi) {
    ull r; asm("mov.b64 %0, {%1, %2};" : "=l"(r)
               : "r"(__float_as_uint(lo)), "r"(__float_as_uint(hi)));
    return r;
}
DI float2 up2(ull v) {
    uint32_t lo, hi; asm("mov.b64 {%0, %1}, %2;" : "=r"(lo), "=r"(hi) : "l"(v));
    return make_float2(__uint_as_float(lo), __uint_as_float(hi));
}
DI float ex2f(float x) { float r; asm("ex2.approx.f32 %0, %1;" : "=f"(r) : "f"(x)); return r; }

// ---------------- kernel 1: grouped 1x1 convs -> k, q, v ----------------
// grid (L/256, G=8, N=4), 256 threads
__global__ void __launch_bounds__(256) qkv_kernel(
    const float* __restrict__ tokens,
    const float* __restrict__ wk, const float* __restrict__ bk,
    const float* __restrict__ wq, const float* __restrict__ bq,
    const float* __restrict__ wv, const float* __restrict__ bv)
{
    __shared__ float swk[16*32], swq[16*32], swv[32*32];
    __shared__ float sbk[16], sbq[16], sbv[32];
    const int g = blockIdx.y, n = blockIdx.z;
    const int tid = threadIdx.x;

    const float* wkg = wk + g*16*32;
    const float* wqg = wq + g*16*32;
    const float* wvg = wv + g*32*32;
    for (int i = tid; i < 512;  i += 256) { swk[i] = wkg[i]; swq[i] = wqg[i]; }
    for (int i = tid; i < 1024; i += 256) { swv[i] = wvg[i]; }
    if (tid < 16) { sbk[tid] = bk[g*16 + tid]; sbq[tid] = bq[g*16 + tid]; }
    if (tid < 32) { sbv[tid] = bv[g*32 + tid]; }
    __syncthreads();

    const int l = blockIdx.x*256 + tid;
    float x[32];
    const float* tp = tokens + (n*CT + g*32)*LSEQ + l;
    #pragma unroll
    for (int i = 0; i < 32; i++) x[i] = tp[i*LSEQ];

    float* kout = g_k + (n*CK + g*16)*LSEQ + l;
    float* qout = g_q + (n*CK + g*16)*LSEQ + l;
    #pragma unroll
    for (int o = 0; o < 16; o++) {
        float sk = sbk[o], sq = sbq[o];
        #pragma unroll
        for (int i = 0; i < 32; i++) {
            sk += swk[o*32 + i] * x[i];
            sq += swq[o*32 + i] * x[i];
        }
        kout[o*LSEQ] = sk;
        qout[o*LSEQ] = sq;
    }
    float* vout = g_v + (n*CT + g*32)*LSEQ + l;
    #pragma unroll
    for (int o = 0; o < 32; o++) {
        float sv = sbv[o];
        #pragma unroll
        for (int i = 0; i < 32; i++) sv += swv[o*32 + i] * x[i];
        vout[o*LSEQ] = sv;
    }
}

// ---------------- kernel 2: attention + residual ----------------
// per (n,h): S[l,m] = sum_c k[c,l] q[c,m]; P = softmax over l (scores are tiny,
// |s|<~0.5 after 1/32 scale, so no max subtraction needed); out[c,m] = sum_l v[c,l] P[l,m].
// grid (L/256, H=16, N=4), 256 threads, one m column per thread, l tiled by 256.
__global__ void __launch_bounds__(256) attn_kernel(const float* __restrict__ tokens)
{
    __shared__ float Ks[256*8];    // [l_local][c] pairs contiguous
    __shared__ float Vs[256*16];
    const int h = blockIdx.y, n = blockIdx.z;
    const int tid = threadIdx.x;
    const float* kp = g_k + (n*NH + h)*8*LSEQ;
    const float* vp = g_v + (n*NH + h)*16*LSEQ;
    const int m = blockIdx.x*256 + tid;

    // fold softmax scale (1/32) and log2(e) into q
    const float qs = 1.4426950408889634f * 0.03125f;
    const float* qp = g_q + (n*NH + h)*8*LSEQ + m;
    ull q2[4];
    #pragma unroll
    for (int c = 0; c < 4; c++)
        q2[c] = pk2(qp[(2*c)*LSEQ] * qs, qp[(2*c + 1)*LSEQ] * qs);

    ull acc[8];
    #pragma unroll
    for (int j = 0; j < 8; j++) acc[j] = 0ull;
    float denom = 0.f;

    for (int t = 0; t < 4; t++) {
        const int l0 = t*256;
        __syncthreads();
        #pragma unroll
        for (int r = 0; r < 8; r++) {
            int idx = r*256 + tid;
            int c = idx >> 8, ll = idx & 255;
            Ks[ll*8 + c] = kp[c*LSEQ + l0 + ll];
        }
        #pragma unroll
        for (int r = 0; r < 16; r++) {
            int idx = r*256 + tid;
            int c = idx >> 8, ll = idx & 255;
            Vs[ll*16 + c] = vp[c*LSEQ + l0 + ll];
        }
        __syncthreads();

        #pragma unroll 2
        for (int ll = 0; ll < 256; ll++) {
            const longlong2 ka = *reinterpret_cast<const longlong2*>(Ks + ll*8);
            const longlong2 kb = *reinterpret_cast<const longlong2*>(Ks + ll*8 + 4);
            ull s2 = mul2((ull)ka.x, q2[0]);
            s2 = fma2((ull)ka.y, q2[1], s2);
            s2 = fma2((ull)kb.x, q2[2], s2);
            s2 = fma2((ull)kb.y, q2[3], s2);
            float2 sf = up2(s2);
            const float p = ex2f(sf.x + sf.y);
            denom += p;
            const ull p2 = pk2(p, p);
            const longlong2 v0 = *reinterpret_cast<const longlong2*>(Vs + ll*16);
            const longlong2 v1 = *reinterpret_cast<const longlong2*>(Vs + ll*16 + 4);
            const longlong2 v2 = *reinterpret_cast<const longlong2*>(Vs + ll*16 + 8);
            const longlong2 v3 = *reinterpret_cast<const longlong2*>(Vs + ll*16 + 12);
            acc[0] = fma2((ull)v0.x, p2, acc[0]);
            acc[1] = fma2((ull)v0.y, p2, acc[1]);
            acc[2] = fma2((ull)v1.x, p2, acc[2]);
            acc[3] = fma2((ull)v1.y, p2, acc[3]);
            acc[4] = fma2((ull)v2.x, p2, acc[4]);
            acc[5] = fma2((ull)v2.y, p2, acc[5]);
            acc[6] = fma2((ull)v3.x, p2, acc[6]);
            acc[7] = fma2((ull)v3.y, p2, acc[7]);
        }
    }

    const float rinv = 1.f / denom;
    const float* t0 = tokens + (n*CT + h*16)*LSEQ + m;
    float*       t1 = g_t1  + (n*CT + h*16)*LSEQ + m;
    #pragma unroll
    for (int j = 0; j < 8; j++) {
        const float2 a = up2(acc[j]);
        t1[(2*j    )*LSEQ] = t0[(2*j    )*LSEQ] + a.x*rinv;
        t1[(2*j + 1)*LSEQ] = t0[(2*j + 1)*LSEQ] + a.y*rinv;
    }
}

// ---------------- kernel 3: LN1 (+ transpose to [r][c]) ----------------
// grid 4096 (one per (n,l)), 256 threads (one per c)
__global__ void __launch_bounds__(256) ln1_kernel(
    const float* __restrict__ g1, const float* __restrict__ be1)
{
    const int b = blockIdx.x;            // n*1024 + l
    const int n = b >> 10, l = b & 1023;
    const int c = threadIdx.x;
    const float val = g_t1[((n*CT + c) << 10) + l];
    float s = val, ss = val*val;
    #pragma unroll
    for (int o = 16; o; o >>= 1) {
        s  += __shfl_xor_sync(0xffffffffu, s, o);
        ss += __shfl_xor_sync(0xffffffffu, ss, o);
    }
    __shared__ float rs[8], rss[8];
    if ((c & 31) == 0) { rs[c >> 5] = s; rss[c >> 5] = ss; }
    __syncthreads();
    s = 0.f; ss = 0.f;
    #pragma unroll
    for (int i = 0; i < 8; i++) { s += rs[i]; ss += rss[i]; }
    const float mu   = s * (1.f/CT);
    const float var  = ss * (1.f/CT) - mu*mu;
    const float rstd = rsqrtf(var + 1e-5f);
    g_xn [b*CT + c] = (val - mu)*rstd*g1[c] + be1[c];
    g_t1t[b*CT + c] = val;
}

// ---------------- kernels 4/5: FFN GEMMs (f32x2 register tiled) ----------------
// C[4096][256] = A[4096][256] * W[256(o)][256(c)]^T + bias ; PHASE 0 applies relu.
// BM=128, BN=64, BK=16; 256 threads; 8x4 outputs/thread (as 4 m-pairs x 4 n).
template<int PHASE>
__global__ void __launch_bounds__(256) gemm_kernel(
    const float* __restrict__ W, const float* __restrict__ bias)
{
    const float* __restrict__ A    = (PHASE == 0) ? g_xn : g_h1;
    float*       __restrict__ Cout = (PHASE == 0) ? g_h1 : g_ffn;
    __shared__ float As[16][128];
    __shared__ float Bs[16][64];
    const int tid = threadIdx.x;
    const int r0 = blockIdx.x * 128;
    const int o0 = blockIdx.y * 64;
    const int m0 = (tid >> 4) * 8;
    const int n0 = (tid & 15) * 4;
    const int am = tid >> 1;
    const int ak = (tid & 1) * 8;
    const int bn = tid >> 2;
    const int bk = (tid & 3) * 4;

    ull acc[4][4];
    #pragma unroll
    for (int i = 0; i < 4; i++)
        #pragma unroll
        for (int j = 0; j < 4; j++) acc[i][j] = 0ull;

    for (int k0 = 0; k0 < 256; k0 += 16) {
        const float4 a0 = *reinterpret_cast<const float4*>(A + (r0 + am)*CT + k0 + ak);
        const float4 a1 = *reinterpret_cast<const float4*>(A + (r0 + am)*CT + k0 + ak + 4);
        const float4 b0 = *reinterpret_cast<const float4*>(W + (o0 + bn)*CT + k0 + bk);
        __syncthreads();
        As[ak+0][am] = a0.x; As[ak+1][am] = a0.y; As[ak+2][am] = a0.z; As[ak+3][am] = a0.w;
        As[ak+4][am] = a1.x; As[ak+5][am] = a1.y; As[ak+6][am] = a1.z; As[ak+7][am] = a1.w;
        Bs[bk+0][bn] = b0.x; Bs[bk+1][bn] = b0.y; Bs[bk+2][bn] = b0.z; Bs[bk+3][bn] = b0.w;
        __syncthreads();
        #pragma unroll
        for (int kk = 0; kk < 16; kk++) {
            const longlong2 apa = *reinterpret_cast<const longlong2*>(&As[kk][m0]);
            const longlong2 apb = *reinterpret_cast<const longlong2*>(&As[kk][m0 + 4]);
            const float4 bv = *reinterpret_cast<const float4*>(&Bs[kk][n0]);
            const ull a2[4] = { (ull)apa.x, (ull)apa.y, (ull)apb.x, (ull)apb.y };
            const ull b2[4] = { pk2(bv.x, bv.x), pk2(bv.y, bv.y),
                                pk2(bv.z, bv.z), pk2(bv.w, bv.w) };
            #pragma unroll
            for (int i = 0; i < 4; i++)
                #pragma unroll
                for (int j = 0; j < 4; j++)
                    acc[i][j] = fma2(a2[i], b2[j], acc[i][j]);
        }
    }

    const float4 bj4 = *reinterpret_cast<const float4*>(bias + o0 + n0);
    #pragma unroll
    for (int i = 0; i < 4; i++) {
        const float2 a0 = up2(acc[i][0]);
        const float2 a1 = up2(acc[i][1]);
        const float2 a2 = up2(acc[i][2]);
        const float2 a3 = up2(acc[i][3]);
        float4 vlo = make_float4(a0.x + bj4.x, a1.x + bj4.y, a2.x + bj4.z, a3.x + bj4.w);
        float4 vhi = make_float4(a0.y + bj4.x, a1.y + bj4.y, a2.y + bj4.z, a3.y + bj4.w);
        if (PHASE == 0) {
            vlo.x = fmaxf(vlo.x, 0.f); vlo.y = fmaxf(vlo.y, 0.f);
            vlo.z = fmaxf(vlo.z, 0.f); vlo.w = fmaxf(vlo.w, 0.f);
            vhi.x = fmaxf(vhi.x, 0.f); vhi.y = fmaxf(vhi.y, 0.f);
            vhi.z = fmaxf(vhi.z, 0.f); vhi.w = fmaxf(vhi.w, 0.f);
        }
        *reinterpret_cast<float4*>(Cout + (r0 + m0 + 2*i    )*CT + o0 + n0) = vlo;
        *reinterpret_cast<float4*>(Cout + (r0 + m0 + 2*i + 1)*CT + o0 + n0) = vhi;
    }
}

// ---------------- kernel 6: residual + LN2 + transpose to output ----------------
__global__ void __launch_bounds__(256) ln2_kernel(
    const float* __restrict__ g2, const float* __restrict__ be2, float* __restrict__ out)
{
    const int b = blockIdx.x;
    const int n = b >> 10, l = b & 1023;
    const int c = threadIdx.x;
    const float val = g_t1t[b*CT + c] + g_ffn[b*CT + c];
    float s = val, ss = val*val;
    #pragma unroll
    for (int o = 16; o; o >>= 1) {
        s  += __shfl_xor_sync(0xffffffffu, s, o);
        ss += __shfl_xor_sync(0xffffffffu, ss, o);
    }
    __shared__ float rs[8], rss[8];
    if ((c & 31) == 0) { rs[c >> 5] = s; rss[c >> 5] = ss; }
    __syncthreads();
    s = 0.f; ss = 0.f;
    #pragma unroll
    for (int i = 0; i < 8; i++) { s += rs[i]; ss += rss[i]; }
    const float mu   = s * (1.f/CT);
    const float var  = ss * (1.f/CT) - mu*mu;
    const float rstd = rsqrtf(var + 1e-5f);
    out[((n*CT + c) << 10) + l] = (val - mu)*rstd*g2[c] + be2[c];
}

// ---------------- launch ----------------
extern "C" void kernel_launch(void* const* d_in, const int* in_sizes, int n_in,
                              void* d_out, int out_size)
{
    const float* tokens = (const float*)d_in[0];
    const float* wk  = (const float*)d_in[1];
    const float* bk  = (const float*)d_in[2];
    const float* wq  = (const float*)d_in[3];
    const float* bq  = (const float*)d_in[4];
    const float* wv  = (const float*)d_in[5];
    const float* bv  = (const float*)d_in[6];
    const float* w1  = (const float*)d_in[7];
    const float* b1  = (const float*)d_in[8];
    const float* w2  = (const float*)d_in[9];
    const float* b2  = (const float*)d_in[10];
    const float* g1  = (const float*)d_in[11];
    const float* be1 = (const float*)d_in[12];
    const float* g2  = (const float*)d_in[13];
    const float* be2 = (const float*)d_in[14];
    float* out = (float*)d_out;

    qkv_kernel <<<dim3(LSEQ/256, 8, NB), 256>>>(tokens, wk, bk, wq, bq, wv, bv);
    attn_kernel<<<dim3(LSEQ/256, NH, NB), 256>>>(tokens);
    ln1_kernel <<<NB*LSEQ, 256>>>(g1, be1);
    gemm_kernel<0><<<dim3(NB*LSEQ/128, CT/64), 256>>>(w1, b1);
    gemm_kernel<1><<<dim3(NB*LSEQ/128, CT/64), 256>>>(w2, b2);
    ln2_kernel <<<NB*LSEQ, 256>>>(g2, be2, out);
}

// round 4
// speedup vs baseline: 1.0374x; 1.0374x over previous
#include <cuda_runtime.h>
#include <cuda_bf16.h>
#include <cstdint>

typedef unsigned long long ull;
#define DI __device__ __forceinline__

constexpr int NB   = 4;
constexpr int CT   = 256;
constexpr int LSEQ = 1024;
constexpr int NH   = 16;
constexpr int CK   = 128;

// ---------------- scratch ----------------
__device__ float g_k  [NB*CK*LSEQ];
__device__ float g_q  [NB*CK*LSEQ];
__device__ float g_v  [NB*CT*LSEQ];
__device__ float g_t1 [NB*CT*LSEQ];   // tokens + kqv, [N][C][L]
__device__ float g_t1t[NB*LSEQ*CT];   // transposed copy, [N*L][C]
__device__ float g_xn [NB*LSEQ*CT];   // LN1 output, [N*L][C]
__device__ float g_h1 [NB*LSEQ*CT];   // FFN hidden
__device__ float g_ffn[NB*LSEQ*CT];   // FFN output

// ---------------- f32x2 helpers ----------------
DI ull fma2(ull a, ull b, ull c) {
    ull d; asm("fma.rn.f32x2 %0, %1, %2, %3;" : "=l"(d) : "l"(a), "l"(b), "l"(c)); return d;
}
DI ull mul2(ull a, ull b) {
    ull d; asm("mul.rn.f32x2 %0, %1, %2;" : "=l"(d) : "l"(a), "l"(b)); return d;
}
DI ull pk2(float lo, float hi) {
    ull r; asm("mov.b64 %0, {%1, %2};" : "=l"(r)
               : "r"(__float_as_uint(lo)), "r"(__float_as_uint(hi)));
    return r;
}
DI float2 up2(ull v) {
    uint32_t lo, hi; asm("mov.b64 {%0, %1}, %2;" : "=r"(lo), "=r"(hi) : "l"(v));
    return make_float2(__uint_as_float(lo), __uint_as_float(hi));
}
DI float ex2f(float x) { float r; asm("ex2.approx.f32 %0, %1;" : "=f"(r) : "f"(x)); return r; }

// ---------------- mma helpers (plain compute_100-legal) ----------------
DI uint32_t smem_u32(const void* p) {
    uint32_t a;
    asm("{ .reg .u64 t; cvta.to.shared.u64 t, %1; cvt.u32.u64 %0, t; }" : "=r"(a) : "l"(p));
    return a;
}
DI void ldm4(uint32_t* r, uint32_t addr) {
    asm volatile("ldmatrix.sync.aligned.m8n8.x4.shared.b16 {%0,%1,%2,%3}, [%4];"
                 : "=r"(r[0]), "=r"(r[1]), "=r"(r[2]), "=r"(r[3]) : "r"(addr));
}
DI void mma16816(float* c, const uint32_t* a, uint32_t b0, uint32_t b1) {
    asm volatile(
        "mma.sync.aligned.m16n8k16.row.col.f32.bf16.bf16.f32 "
        "{%0,%1,%2,%3}, {%4,%5,%6,%7}, {%8,%9}, {%0,%1,%2,%3};"
        : "+f"(c[0]), "+f"(c[1]), "+f"(c[2]), "+f"(c[3])
        : "r"(a[0]), "r"(a[1]), "r"(a[2]), "r"(a[3]), "r"(b0), "r"(b1));
}
DI uint32_t sw128(uint32_t b) { return b ^ ((b >> 3) & 0x70); }
DI void sts32(uint32_t addr, uint32_t v) {
    asm volatile("st.shared.b32 [%0], %1;" :: "r"(addr), "r"(v));
}
DI uint32_t pack_bf16(float x0, float x1) {
    __nv_bfloat16 h0 = __float2bfloat16(x0), h1 = __float2bfloat16(x1);
    return (uint32_t)__bfloat16_as_ushort(h0) | ((uint32_t)__bfloat16_as_ushort(h1) << 16);
}
DI float bf16lo(float x) { return x - __bfloat162float(__float2bfloat16(x)); }

// ---------------- kernel 1: grouped 1x1 convs -> k, q, v ----------------
__global__ void __launch_bounds__(256) qkv_kernel(
    const float* __restrict__ tokens,
    const float* __restrict__ wk, const float* __restrict__ bk,
    const float* __restrict__ wq, const float* __restrict__ bq,
    const float* __restrict__ wv, const float* __restrict__ bv)
{
    __shared__ float swk[16*32], swq[16*32], swv[32*32];
    __shared__ float sbk[16], sbq[16], sbv[32];
    const int g = blockIdx.y, n = blockIdx.z;
    const int tid = threadIdx.x;

    const float* wkg = wk + g*16*32;
    const float* wqg = wq + g*16*32;
    const float* wvg = wv + g*32*32;
    for (int i = tid; i < 512;  i += 256) { swk[i] = wkg[i]; swq[i] = wqg[i]; }
    for (int i = tid; i < 1024; i += 256) { swv[i] = wvg[i]; }
    if (tid < 16) { sbk[tid] = bk[g*16 + tid]; sbq[tid] = bq[g*16 + tid]; }
    if (tid < 32) { sbv[tid] = bv[g*32 + tid]; }
    __syncthreads();

    const int l = blockIdx.x*256 + tid;
    float x[32];
    const float* tp = tokens + (n*CT + g*32)*LSEQ + l;
    #pragma unroll
    for (int i = 0; i < 32; i++) x[i] = tp[i*LSEQ];

    float* kout = g_k + (n*CK + g*16)*LSEQ + l;
    float* qout = g_q + (n*CK + g*16)*LSEQ + l;
    #pragma unroll
    for (int o = 0; o < 16; o++) {
        float sk = sbk[o], sq = sbq[o];
        #pragma unroll
        for (int i = 0; i < 32; i++) {
            sk += swk[o*32 + i] * x[i];
            sq += swq[o*32 + i] * x[i];
        }
        kout[o*LSEQ] = sk;
        qout[o*LSEQ] = sq;
    }
    float* vout = g_v + (n*CT + g*32)*LSEQ + l;
    #pragma unroll
    for (int o = 0; o < 32; o++) {
        float sv = sbv[o];
        #pragma unroll
        for (int i = 0; i < 32; i++) sv += swv[o*32 + i] * x[i];
        vout[o*LSEQ] = sv;
    }
}

// ---------------- kernel 2: attention + residual (128 thr, 2 m-cols each) ----------------
__global__ void __launch_bounds__(128) attn_kernel(const float* __restrict__ tokens)
{
    __shared__ float Ks[256*8];
    __shared__ float Vs[256*16];
    const int h = blockIdx.y, n = blockIdx.z;
    const int tid = threadIdx.x;
    const float* kp = g_k + (n*NH + h)*8*LSEQ;
    const float* vp = g_v + (n*NH + h)*16*LSEQ;
    const int m0 = blockIdx.x*256 + tid;
    const int m1 = m0 + 128;

    const float qs = 1.4426950408889634f * 0.03125f;   // log2(e)/sqrt(L)
    const float* qp = g_q + (n*NH + h)*8*LSEQ;
    ull qa[4], qb[4];
    #pragma unroll
    for (int c = 0; c < 4; c++) {
        qa[c] = pk2(qp[(2*c)*LSEQ + m0]*qs, qp[(2*c + 1)*LSEQ + m0]*qs);
        qb[c] = pk2(qp[(2*c)*LSEQ + m1]*qs, qp[(2*c + 1)*LSEQ + m1]*qs);
    }

    ull aa[8], ab[8];
    #pragma unroll
    for (int j = 0; j < 8; j++) { aa[j] = 0ull; ab[j] = 0ull; }
    float da = 0.f, db = 0.f;

    for (int t = 0; t < 4; t++) {
        const int l0 = t*256;
        __syncthreads();
        for (int idx = tid; idx < 2048; idx += 128) {
            const int c = idx >> 8, ll = idx & 255;
            Ks[ll*8 + c] = kp[c*LSEQ + l0 + ll];
        }
        for (int idx = tid; idx < 4096; idx += 128) {
            const int c = idx >> 8, ll = idx & 255;
            Vs[ll*16 + c] = vp[c*LSEQ + l0 + ll];
        }
        __syncthreads();

        #pragma unroll 2
        for (int ll = 0; ll < 256; ll++) {
            const longlong2 ka = *reinterpret_cast<const longlong2*>(Ks + ll*8);
            const longlong2 kb = *reinterpret_cast<const longlong2*>(Ks + ll*8 + 4);
            ull sa = mul2((ull)ka.x, qa[0]);
            ull sb = mul2((ull)ka.x, qb[0]);
            sa = fma2((ull)ka.y, qa[1], sa);  sb = fma2((ull)ka.y, qb[1], sb);
            sa = fma2((ull)kb.x, qa[2], sa);  sb = fma2((ull)kb.x, qb[2], sb);
            sa = fma2((ull)kb.y, qa[3], sa);  sb = fma2((ull)kb.y, qb[3], sb);
            float2 fa = up2(sa), fb = up2(sb);
            const float pa = ex2f(fa.x + fa.y);
            const float pb = ex2f(fb.x + fb.y);
            da += pa; db += pb;
            const ull p2a = pk2(pa, pa), p2b = pk2(pb, pb);
            const longlong2 v0 = *reinterpret_cast<const longlong2*>(Vs + ll*16);
            const longlong2 v1 = *reinterpret_cast<const longlong2*>(Vs + ll*16 + 4);
            const longlong2 v2 = *reinterpret_cast<const longlong2*>(Vs + ll*16 + 8);
            const longlong2 v3 = *reinterpret_cast<const longlong2*>(Vs + ll*16 + 12);
            aa[0] = fma2((ull)v0.x, p2a, aa[0]);  ab[0] = fma2((ull)v0.x, p2b, ab[0]);
            aa[1] = fma2((ull)v0.y, p2a, aa[1]);  ab[1] = fma2((ull)v0.y, p2b, ab[1]);
            aa[2] = fma2((ull)v1.x, p2a, aa[2]);  ab[2] = fma2((ull)v1.x, p2b, ab[2]);
            aa[3] = fma2((ull)v1.y, p2a, aa[3]);  ab[3] = fma2((ull)v1.y, p2b, ab[3]);
            aa[4] = fma2((ull)v2.x, p2a, aa[4]);  ab[4] = fma2((ull)v2.x, p2b, ab[4]);
            aa[5] = fma2((ull)v2.y, p2a, aa[5]);  ab[5] = fma2((ull)v2.y, p2b, ab[5]);
            aa[6] = fma2((ull)v3.x, p2a, aa[6]);  ab[6] = fma2((ull)v3.x, p2b, ab[6]);
            aa[7] = fma2((ull)v3.y, p2a, aa[7]);  ab[7] = fma2((ull)v3.y, p2b, ab[7]);
        }
    }

    const float ra = 1.f / da, rb = 1.f / db;
    const float* t0 = tokens + (n*CT + h*16)*LSEQ;
    float*       t1 = g_t1  + (n*CT + h*16)*LSEQ;
    #pragma unroll
    for (int j = 0; j < 8; j++) {
        const float2 va = up2(aa[j]);
        const float2 vb = up2(ab[j]);
        t1[(2*j    )*LSEQ + m0] = t0[(2*j    )*LSEQ + m0] + va.x*ra;
        t1[(2*j + 1)*LSEQ + m0] = t0[(2*j + 1)*LSEQ + m0] + va.y*ra;
        t1[(2*j    )*LSEQ + m1] = t0[(2*j    )*LSEQ + m1] + vb.x*rb;
        t1[(2*j + 1)*LSEQ + m1] = t0[(2*j + 1)*LSEQ + m1] + vb.y*rb;
    }
}

// ---------------- kernel 3: LN1 (+ transpose to [r][c]) ----------------
__global__ void __launch_bounds__(256) ln1_kernel(
    const float* __restrict__ g1, const float* __restrict__ be1)
{
    const int b = blockIdx.x;
    const int n = b >> 10, l = b & 1023;
    const int c = threadIdx.x;
    const float val = g_t1[((n*CT + c) << 10) + l];
    float s = val, ss = val*val;
    #pragma unroll
    for (int o = 16; o; o >>= 1) {
        s  += __shfl_xor_sync(0xffffffffu, s, o);
        ss += __shfl_xor_sync(0xffffffffu, ss, o);
    }
    __shared__ float rs[8], rss[8];
    if ((c & 31) == 0) { rs[c >> 5] = s; rss[c >> 5] = ss; }
    __syncthreads();
    s = 0.f; ss = 0.f;
    #pragma unroll
    for (int i = 0; i < 8; i++) { s += rs[i]; ss += rss[i]; }
    const float mu   = s * (1.f/CT);
    const float var  = ss * (1.f/CT) - mu*mu;
    const float rstd = rsqrtf(var + 1e-5f);
    g_xn [b*CT + c] = (val - mu)*rstd*g1[c] + be1[c];
    g_t1t[b*CT + c] = val;
}

// ---------------- kernels 4/5: FFN GEMMs via mma.sync bf16 hi/lo split ----------------
// C[4096][256] = A[4096][256] * W[256(o)][256(c)]^T + bias (PHASE 0 -> relu).
// Block: 64 rows x 64 out-cols, 256 threads (8 warps as 4m x 2n, warp = 16x32).
// K chunked by 64, A/W split into bf16 hi+lo, 3 mma passes (Ah*Wh + Ah*Wl + Al*Wh).
template<int PHASE>
__global__ void __launch_bounds__(256) gemm_mma_kernel(
    const float* __restrict__ W, const float* __restrict__ bias)
{
    const float* __restrict__ A    = (PHASE == 0) ? g_xn : g_h1;
    float*       __restrict__ Cout = (PHASE == 0) ? g_h1 : g_ffn;

    __shared__ __align__(1024) __nv_bfloat16 aHi[64*64], aLo[64*64], wHi[64*64], wLo[64*64];
    const uint32_t aHiB = smem_u32(aHi), aLoB = smem_u32(aLo);
    const uint32_t wHiB = smem_u32(wHi), wLoB = smem_u32(wLo);

    const int tid  = threadIdx.x;
    const int wid  = tid >> 5;
    const int lane = tid & 31;
    const int r0 = blockIdx.x * 64;
    const int o0 = blockIdx.y * 64;
    const int warp_m = (wid >> 1) * 16;
    const int warp_n = (wid & 1) * 32;

    // fill mapping: row = tid>>2 (0..63), 16 consecutive k at (tid&3)*16
    const int frow = tid >> 2;
    const int fc0  = (tid & 3) * 16;

    float acc[4][4];
    #pragma unroll
    for (int j = 0; j < 4; j++)
        #pragma unroll
        for (int i = 0; i < 4; i++) acc[j][i] = 0.f;

    // ldmatrix source addresses (same formula for A and W tiles)
    const uint32_t lrow = lane & 15;
    const uint32_t lcol = (lane >> 4) << 3;   // 0 or 8 (k offset within 16)

    float4 pa[4], pw[4];
    {
        const float4* ap = reinterpret_cast<const float4*>(A + (r0 + frow)*CT + fc0);
        const float4* wp = reinterpret_cast<const float4*>(W + (o0 + frow)*CT + fc0);
        #pragma unroll
        for (int q = 0; q < 4; q++) { pa[q] = __ldg(ap + q); pw[q] = __ldg(wp + q); }
    }

    for (int chunk = 0; chunk < 4; chunk++) {
        __syncthreads();
        #pragma unroll
        for (int q = 0; q < 4; q++) {
            const uint32_t off0 = sw128((uint32_t)(frow*128 + (fc0 + q*4)*2));
            const uint32_t off1 = off0 + 4;   // same 16B unit -> same swizzle
            sts32(aHiB + off0, pack_bf16(pa[q].x, pa[q].y));
            sts32(aHiB + off1, pack_bf16(pa[q].z, pa[q].w));
            sts32(aLoB + off0, pack_bf16(bf16lo(pa[q].x), bf16lo(pa[q].y)));
            sts32(aLoB + off1, pack_bf16(bf16lo(pa[q].z), bf16lo(pa[q].w)));
            sts32(wHiB + off0, pack_bf16(pw[q].x, pw[q].y));
            sts32(wHiB + off1, pack_bf16(pw[q].z, pw[q].w));
            sts32(wLoB + off0, pack_bf16(bf16lo(pw[q].x), bf16lo(pw[q].y)));
            sts32(wLoB + off1, pack_bf16(bf16lo(pw[q].z), bf16lo(pw[q].w)));
        }
        __syncthreads();

        if (chunk < 3) {
            const int k0n = (chunk + 1) * 64;
            const float4* ap = reinterpret_cast<const float4*>(A + (r0 + frow)*CT + k0n + fc0);
            const float4* wp = reinterpret_cast<const float4*>(W + (o0 + frow)*CT + k0n + fc0);
            #pragma unroll
            for (int q = 0; q < 4; q++) { pa[q] = __ldg(ap + q); pw[q] = __ldg(wp + q); }
        }

        #pragma unroll
        for (int kk = 0; kk < 64; kk += 16) {
            const uint32_t aoff = sw128((uint32_t)((warp_m + lrow)*128 + (kk + lcol)*2));
            uint32_t ah[4], al[4];
            ldm4(ah, aHiB + aoff);
            ldm4(al, aLoB + aoff);
            uint32_t bh[2][4], bl[2][4];
            #pragma unroll
            for (int nb = 0; nb < 2; nb++) {
                const uint32_t boff =
                    sw128((uint32_t)((warp_n + nb*16 + lrow)*128 + (kk + lcol)*2));
                ldm4(bh[nb], wHiB + boff);
                ldm4(bl[nb], wLoB + boff);
            }
            #pragma unroll
            for (int j = 0; j < 4; j++) {
                const int nb = j >> 1, jj = j & 1;
                mma16816(acc[j], ah, bh[nb][jj], bh[nb][2 + jj]);
                mma16816(acc[j], ah, bl[nb][jj], bl[nb][2 + jj]);
                mma16816(acc[j], al, bh[nb][jj], bh[nb][2 + jj]);
            }
        }
    }

    // epilogue: c0,c1 -> row (lane>>2), cols (lane&3)*2 + {0,1}; c2,c3 -> row+8
    const int crow = r0 + warp_m + (lane >> 2);
    #pragma unroll
    for (int j = 0; j < 4; j++) {
        const int col = o0 + warp_n + j*8 + (lane & 3)*2;
        const float b0 = __ldg(bias + col), b1 = __ldg(bias + col + 1);
        float v0 = acc[j][0] + b0, v1 = acc[j][1] + b1;
        float v2 = acc[j][2] + b0, v3 = acc[j][3] + b1;
        if (PHASE == 0) {
            v0 = fmaxf(v0, 0.f); v1 = fmaxf(v1, 0.f);
            v2 = fmaxf(v2, 0.f); v3 = fmaxf(v3, 0.f);
        }
        Cout[ crow      *CT + col    ] = v0;
        Cout[ crow      *CT + col + 1] = v1;
        Cout[(crow + 8) *CT + col    ] = v2;
        Cout[(crow + 8) *CT + col + 1] = v3;
    }
}

// ---------------- kernel 6: residual + LN2 + transpose to output ----------------
__global__ void __launch_bounds__(256) ln2_kernel(
    const float* __restrict__ g2, const float* __restrict__ be2, float* __restrict__ out)
{
    const int b = blockIdx.x;
    const int n = b >> 10, l = b & 1023;
    const int c = threadIdx.x;
    const float val = g_t1t[b*CT + c] + g_ffn[b*CT + c];
    float s = val, ss = val*val;
    #pragma unroll
    for (int o = 16; o; o >>= 1) {
        s  += __shfl_xor_sync(0xffffffffu, s, o);
        ss += __shfl_xor_sync(0xffffffffu, ss, o);
    }
    __shared__ float rs[8], rss[8];
    if ((c & 31) == 0) { rs[c >> 5] = s; rss[c >> 5] = ss; }
    __syncthreads();
    s = 0.f; ss = 0.f;
    #pragma unroll
    for (int i = 0; i < 8; i++) { s += rs[i]; ss += rss[i]; }
    const float mu   = s * (1.f/CT);
    const float var  = ss * (1.f/CT) - mu*mu;
    const float rstd = rsqrtf(var + 1e-5f);
    out[((n*CT + c) << 10) + l] = (val - mu)*rstd*g2[c] + be2[c];
}

// ---------------- launch ----------------
extern "C" void kernel_launch(void* const* d_in, const int* in_sizes, int n_in,
                              void* d_out, int out_size)
{
    const float* tokens = (const float*)d_in[0];
    const float* wk  = (const float*)d_in[1];
    const float* bk  = (const float*)d_in[2];
    const float* wq  = (const float*)d_in[3];
    const float* bq  = (const float*)d_in[4];
    const float* wv  = (const float*)d_in[5];
    const float* bv  = (const float*)d_in[6];
    const float* w1  = (const float*)d_in[7];
    const float* b1  = (const float*)d_in[8];
    const float* w2  = (const float*)d_in[9];
    const float* b2  = (const float*)d_in[10];
    const float* g1  = (const float*)d_in[11];
    const float* be1 = (const float*)d_in[12];
    const float* g2  = (const float*)d_in[13];
    const float* be2 = (const float*)d_in[14];
    float* out = (float*)d_out;

    qkv_kernel <<<dim3(LSEQ/256, 8, NB), 256>>>(tokens, wk, bk, wq, bq, wv, bv);
    attn_kernel<<<dim3(LSEQ/256, NH, NB), 128>>>(tokens);
    ln1_kernel <<<NB*LSEQ, 256>>>(g1, be1);
    gemm_mma_kernel<0><<<dim3(NB*LSEQ/64, CT/64), 256>>>(w1, b1);
    gemm_mma_kernel<1><<<dim3(NB*LSEQ/64, CT/64), 256>>>(w2, b2);
    ln2_kernel <<<NB*LSEQ, 256>>>(g2, be2, out);
}